// round 1
// baseline (speedup 1.0000x reference)
#include <cuda_runtime.h>
#include <math.h>

#define SEQ  2048
#define DM   1024
#define NH   16
#define HD   64
#define DFF  4096

// ---------------- scratch (no allocation allowed) ----------------
__device__ float g_normed [SEQ * DM];
__device__ float g_qkv    [SEQ * 3 * DM];
__device__ float g_q      [NH * SEQ * HD];
__device__ float g_k      [NH * SEQ * HD];
__device__ float g_v      [NH * SEQ * HD];
__device__ float g_attn   [SEQ * DM];
__device__ float g_x2     [SEQ * DM];
__device__ float g_normed2[SEQ * DM];
__device__ float g_ffh    [SEQ * DFF];

// ---------------- LayerNorm: one block per row, 256 thr, float4 ----------------
__global__ __launch_bounds__(256) void ln_kernel(
    const float* __restrict__ x, const float* __restrict__ g,
    const float* __restrict__ b, float* __restrict__ out)
{
    int row = blockIdx.x;
    int tid = threadIdx.x;
    const float* xr = x + (size_t)row * DM;
    float4 xv = reinterpret_cast<const float4*>(xr)[tid];
    float s  = xv.x + xv.y + xv.z + xv.w;
    float sq = xv.x*xv.x + xv.y*xv.y + xv.z*xv.z + xv.w*xv.w;

    __shared__ float sh1[256], sh2[256];
    sh1[tid] = s; sh2[tid] = sq;
    __syncthreads();
    #pragma unroll
    for (int o = 128; o > 0; o >>= 1) {
        if (tid < o) { sh1[tid] += sh1[tid + o]; sh2[tid] += sh2[tid + o]; }
        __syncthreads();
    }
    float mu   = sh1[0] * (1.0f / DM);
    float var  = sh2[0] * (1.0f / DM) - mu * mu;
    float rstd = rsqrtf(var + 1e-5f);

    float4 gv = reinterpret_cast<const float4*>(g)[tid];
    float4 bv = reinterpret_cast<const float4*>(b)[tid];
    float4 o4;
    o4.x = (xv.x - mu) * rstd * gv.x + bv.x;
    o4.y = (xv.y - mu) * rstd * gv.y + bv.y;
    o4.z = (xv.z - mu) * rstd * gv.z + bv.z;
    o4.w = (xv.w - mu) * rstd * gv.w + bv.w;
    reinterpret_cast<float4*>(out + (size_t)row * DM)[tid] = o4;
}

// ---------------- SGEMM 128x128 tile, K-step 8, 256 thr, 8x8 per thread --------
// OP = 0: C = A*B + bias
// OP = 1: C = A*B + bias + res
// OP = 2: C = gelu(A*B + bias)   (exact gelu, erf)
template<int OP>
__global__ __launch_bounds__(256) void sgemm_kernel(
    const float* __restrict__ A, const float* __restrict__ B,
    const float* __restrict__ bias, const float* __restrict__ res,
    float* __restrict__ C, int M, int N, int K)
{
    __shared__ __align__(16) float As[8][128];
    __shared__ __align__(16) float Bs[8][128];

    int tid = threadIdx.x;
    int tx = tid & 15;         // 0..15 -> 8 cols each
    int ty = tid >> 4;         // 0..15 -> 8 rows each
    int m0 = blockIdx.y * 128;
    int n0 = blockIdx.x * 128;

    float acc[8][8] = {};

    int arow = tid >> 1;               // 0..127
    int acg  = (tid & 1) * 4;          // 0 or 4
    int brow = tid >> 5;               // 0..7
    int bcol = (tid & 31) * 4;         // 0..124

    const float* Aptr = A + (size_t)(m0 + arow) * K + acg;
    const float* Bptr = B + (size_t)brow * N + n0 + bcol;

    for (int k0 = 0; k0 < K; k0 += 8) {
        float4 av = *reinterpret_cast<const float4*>(Aptr + k0);
        float4 bv = *reinterpret_cast<const float4*>(Bptr + (size_t)k0 * N);
        __syncthreads();   // prior compute done before overwriting smem
        As[acg + 0][arow] = av.x;
        As[acg + 1][arow] = av.y;
        As[acg + 2][arow] = av.z;
        As[acg + 3][arow] = av.w;
        *reinterpret_cast<float4*>(&Bs[brow][bcol]) = bv;
        __syncthreads();

        #pragma unroll
        for (int kk = 0; kk < 8; kk++) {
            float a[8], bb[8];
            #pragma unroll
            for (int i = 0; i < 8; i++) a[i]  = As[kk][ty * 8 + i];
            #pragma unroll
            for (int j = 0; j < 8; j++) bb[j] = Bs[kk][tx * 8 + j];
            #pragma unroll
            for (int i = 0; i < 8; i++)
                #pragma unroll
                for (int j = 0; j < 8; j++)
                    acc[i][j] += a[i] * bb[j];
        }
    }

    // epilogue
    int colb = n0 + tx * 8;
    float bv8[8];
    #pragma unroll
    for (int j = 0; j < 8; j++) bv8[j] = bias[colb + j];

    #pragma unroll
    for (int i = 0; i < 8; i++) {
        int row = m0 + ty * 8 + i;
        float v[8];
        #pragma unroll
        for (int j = 0; j < 8; j++) {
            v[j] = acc[i][j] + bv8[j];
            if (OP == 1) v[j] += res[(size_t)row * N + colb + j];
            if (OP == 2) v[j] = 0.5f * v[j] * (1.0f + erff(v[j] * 0.70710678118654752f));
        }
        float4* cp = reinterpret_cast<float4*>(C + (size_t)row * N + colb);
        cp[0] = make_float4(v[0], v[1], v[2], v[3]);
        cp[1] = make_float4(v[4], v[5], v[6], v[7]);
    }
}

// ---------------- split qkv, L2-normalize q,k per (l,h); relayout to [H,L,64] --
__global__ __launch_bounds__(256) void qkvnorm_kernel(
    const float* __restrict__ qkv, float* __restrict__ Q,
    float* __restrict__ Km, float* __restrict__ V)
{
    int gw   = (blockIdx.x * blockDim.x + threadIdx.x) >> 5;
    int lane = threadIdx.x & 31;
    int l = gw >> 4;     // / NH
    int h = gw & 15;     // % NH

    const float* base = qkv + (size_t)l * (3 * DM);
    size_t oidx = ((size_t)h * SEQ + l) * HD + lane * 2;

    // q: normalize then * 0.125 (head_dim^-0.5)
    float2 qv = *reinterpret_cast<const float2*>(base + h * HD + lane * 2);
    float ssq = qv.x * qv.x + qv.y * qv.y;
    #pragma unroll
    for (int o = 16; o > 0; o >>= 1) ssq += __shfl_xor_sync(0xffffffffu, ssq, o);
    float scq = 0.125f / fmaxf(sqrtf(ssq), 1e-12f);
    *reinterpret_cast<float2*>(Q + oidx) = make_float2(qv.x * scq, qv.y * scq);

    // k: normalize
    float2 kv = *reinterpret_cast<const float2*>(base + DM + h * HD + lane * 2);
    float ssk = kv.x * kv.x + kv.y * kv.y;
    #pragma unroll
    for (int o = 16; o > 0; o >>= 1) ssk += __shfl_xor_sync(0xffffffffu, ssk, o);
    float sck = 1.0f / fmaxf(sqrtf(ssk), 1e-12f);
    *reinterpret_cast<float2*>(Km + oidx) = make_float2(kv.x * sck, kv.y * sck);

    // v: copy / relayout
    float2 vv = *reinterpret_cast<const float2*>(base + 2 * DM + h * HD + lane * 2);
    *reinterpret_cast<float2*>(V + oidx) = vv;
}

// ---------------- attention: scores clipped to [-10,10] => no online max ------
// grid (SEQ/128, NH), 128 threads, 1 query per thread, 64-key smem tiles
__global__ __launch_bounds__(128) void attn_kernel(
    const float* __restrict__ Q, const float* __restrict__ Km,
    const float* __restrict__ V, const float* __restrict__ lcc,
    float* __restrict__ out)
{
    __shared__ __align__(16) float ks[64 * 64];
    __shared__ __align__(16) float vs[64 * 64];
    __shared__ float lccs[64];

    int h   = blockIdx.y;
    int tid = threadIdx.x;
    int l   = blockIdx.x * 128 + tid;

    const float* qp = Q + ((size_t)h * SEQ + l) * HD;
    float q[64];
    #pragma unroll
    for (int d = 0; d < 64; d++) q[d] = qp[d];

    float myl = lcc[l] * 0.05f;   // 0.5 * LCC_SCALE
    float acc[64] = {};
    float denom = 0.0f;

    for (int kb = 0; kb < SEQ; kb += 64) {
        __syncthreads();
        const float* kp = Km + ((size_t)h * SEQ + kb) * HD;
        const float* vp = V  + ((size_t)h * SEQ + kb) * HD;
        #pragma unroll
        for (int t = 0; t < 8; t++) {
            int f4 = t * 128 + tid;   // 1024 float4 = 4096 floats, contiguous tile
            reinterpret_cast<float4*>(ks)[f4] = reinterpret_cast<const float4*>(kp)[f4];
            reinterpret_cast<float4*>(vs)[f4] = reinterpret_cast<const float4*>(vp)[f4];
        }
        if (tid < 64) lccs[tid] = lcc[kb + tid] * 0.05f;
        __syncthreads();

        #pragma unroll 1
        for (int j = 0; j < 64; j++) {
            const float* kr = ks + j * 64;
            float s0 = 0.f, s1 = 0.f, s2 = 0.f, s3 = 0.f;
            #pragma unroll
            for (int kk = 0; kk < 64; kk += 4) {
                s0 += q[kk + 0] * kr[kk + 0];
                s1 += q[kk + 1] * kr[kk + 1];
                s2 += q[kk + 2] * kr[kk + 2];
                s3 += q[kk + 3] * kr[kk + 3];
            }
            float s = (s0 + s1) + (s2 + s3) + myl + lccs[j];
            s = fminf(10.0f, fmaxf(-10.0f, s));
            float p = expf(s);
            denom += p;
            const float* vr = vs + j * 64;
            #pragma unroll
            for (int d = 0; d < 64; d++) acc[d] += p * vr[d];
        }
    }

    float inv = 1.0f / denom;
    float* op = out + (size_t)l * DM + h * 64;
    #pragma unroll
    for (int d = 0; d < 64; d++) op[d] = acc[d] * inv;
}

// ---------------- launch --------------------------------------------------------
extern "C" void kernel_launch(void* const* d_in, const int* in_sizes, int n_in,
                              void* d_out, int out_size)
{
    const float* x     = (const float*)d_in[0];
    const float* lcc   = (const float*)d_in[1];
    const float* w_qkv = (const float*)d_in[2];
    const float* b_qkv = (const float*)d_in[3];
    const float* w_out = (const float*)d_in[4];
    const float* b_out = (const float*)d_in[5];
    const float* ln1_g = (const float*)d_in[6];
    const float* ln1_b = (const float*)d_in[7];
    const float* ln2_g = (const float*)d_in[8];
    const float* ln2_b = (const float*)d_in[9];
    const float* w_ff1 = (const float*)d_in[10];
    const float* b_ff1 = (const float*)d_in[11];
    const float* w_ff2 = (const float*)d_in[12];
    const float* b_ff2 = (const float*)d_in[13];
    float* out = (float*)d_out;

    float *normed, *qkv, *q, *k, *v, *attn, *x2, *normed2, *ffh;
    cudaGetSymbolAddress((void**)&normed,  g_normed);
    cudaGetSymbolAddress((void**)&qkv,     g_qkv);
    cudaGetSymbolAddress((void**)&q,       g_q);
    cudaGetSymbolAddress((void**)&k,       g_k);
    cudaGetSymbolAddress((void**)&v,       g_v);
    cudaGetSymbolAddress((void**)&attn,    g_attn);
    cudaGetSymbolAddress((void**)&x2,      g_x2);
    cudaGetSymbolAddress((void**)&normed2, g_normed2);
    cudaGetSymbolAddress((void**)&ffh,     g_ffh);

    // 1. LN1
    ln_kernel<<<SEQ, 256>>>(x, ln1_g, ln1_b, normed);
    // 2. QKV projection: [2048,1024] @ [1024,3072]
    sgemm_kernel<0><<<dim3(3 * DM / 128, SEQ / 128), 256>>>(
        normed, w_qkv, b_qkv, nullptr, qkv, SEQ, 3 * DM, DM);
    // 3. split + cosine-normalize + relayout
    qkvnorm_kernel<<<(SEQ * NH * 32) / 256, 256>>>(qkv, q, k, v);
    // 4. attention
    attn_kernel<<<dim3(SEQ / 128, NH), 128>>>(q, k, v, lcc, attn);
    // 5. out projection + residual: x2 = x + attn @ w_out + b_out
    sgemm_kernel<1><<<dim3(DM / 128, SEQ / 128), 256>>>(
        attn, w_out, b_out, x, x2, SEQ, DM, DM);
    // 6. LN2
    ln_kernel<<<SEQ, 256>>>(x2, ln2_g, ln2_b, normed2);
    // 7. FF1 + exact GELU
    sgemm_kernel<2><<<dim3(DFF / 128, SEQ / 128), 256>>>(
        normed2, w_ff1, b_ff1, nullptr, ffh, SEQ, DFF, DM);
    // 8. FF2 + residual -> out
    sgemm_kernel<1><<<dim3(DM / 128, SEQ / 128), 256>>>(
        ffh, w_ff2, b_ff2, x2, out, SEQ, DM, DFF);
}

// round 2
// speedup vs baseline: 2.0642x; 2.0642x over previous
#include <cuda_runtime.h>
#include <math.h>

#define SEQ  2048
#define DM   1024
#define NH   16
#define HD   64
#define DFF  4096

// ---------------- scratch (no allocation allowed) ----------------
__device__ float g_normed [SEQ * DM];
__device__ float g_qkv    [SEQ * 3 * DM];
__device__ float g_q      [NH * SEQ * HD];
__device__ float g_k      [NH * SEQ * HD];
__device__ float g_v      [NH * SEQ * HD];
__device__ float g_attn   [SEQ * DM];
__device__ float g_x2     [SEQ * DM];
__device__ float g_normed2[SEQ * DM];
__device__ float g_ffh    [SEQ * DFF];

// ---------------- LayerNorm ----------------
__global__ __launch_bounds__(256) void ln_kernel(
    const float* __restrict__ x, const float* __restrict__ g,
    const float* __restrict__ b, float* __restrict__ out)
{
    int row = blockIdx.x;
    int tid = threadIdx.x;
    const float* xr = x + (size_t)row * DM;
    float4 xv = reinterpret_cast<const float4*>(xr)[tid];
    float s  = xv.x + xv.y + xv.z + xv.w;
    float sq = xv.x*xv.x + xv.y*xv.y + xv.z*xv.z + xv.w*xv.w;

    __shared__ float sh1[256], sh2[256];
    sh1[tid] = s; sh2[tid] = sq;
    __syncthreads();
    #pragma unroll
    for (int o = 128; o > 0; o >>= 1) {
        if (tid < o) { sh1[tid] += sh1[tid + o]; sh2[tid] += sh2[tid + o]; }
        __syncthreads();
    }
    float mu   = sh1[0] * (1.0f / DM);
    float var  = sh2[0] * (1.0f / DM) - mu * mu;
    float rstd = rsqrtf(var + 1e-5f);

    float4 gv = reinterpret_cast<const float4*>(g)[tid];
    float4 bv = reinterpret_cast<const float4*>(b)[tid];
    float4 o4;
    o4.x = (xv.x - mu) * rstd * gv.x + bv.x;
    o4.y = (xv.y - mu) * rstd * gv.y + bv.y;
    o4.z = (xv.z - mu) * rstd * gv.z + bv.z;
    o4.w = (xv.w - mu) * rstd * gv.w + bv.w;
    reinterpret_cast<float4*>(out + (size_t)row * DM)[tid] = o4;
}

// ---------------- tf32 helpers ----------------
__device__ __forceinline__ float tf32r(float x) {
    float y;
    asm("cvt.rna.tf32.f32 %0, %1;" : "=f"(y) : "f"(x));
    return y;
}
__device__ __forceinline__ float4 cvt4(float4 v) {
    v.x = tf32r(v.x); v.y = tf32r(v.y); v.z = tf32r(v.z); v.w = tf32r(v.w);
    return v;
}
__device__ __forceinline__ void mma8(float* d, const float* a, const float* b) {
    asm volatile(
        "mma.sync.aligned.m16n8k8.row.col.f32.tf32.tf32.f32 "
        "{%0,%1,%2,%3}, {%4,%5,%6,%7}, {%8,%9}, {%0,%1,%2,%3};\n"
        : "+f"(d[0]), "+f"(d[1]), "+f"(d[2]), "+f"(d[3])
        : "r"(__float_as_uint(a[0])), "r"(__float_as_uint(a[1])),
          "r"(__float_as_uint(a[2])), "r"(__float_as_uint(a[3])),
          "r"(__float_as_uint(b[0])), "r"(__float_as_uint(b[1])));
}

// ---------------- tf32 MMA GEMM: 128x128 tile, BK=16, double buffered --------
// OP = 0: C = A*B + bias
// OP = 1: C = A*B + bias + res
// OP = 2: C = gelu(A*B + bias)   (exact gelu, erf)
// 8 warps: 4 in m x 2 in n; warp tile 32x64 -> 2 m-tiles(16) x 8 n-tiles(8)
template<int OP>
__global__ __launch_bounds__(256) void mma_gemm(
    const float* __restrict__ A, const float* __restrict__ B,
    const float* __restrict__ bias, const float* __restrict__ res,
    float* __restrict__ C, int M, int N, int K)
{
    __shared__ __align__(16) float As[2][128][20];   // 20 ≡ 20 mod 32: frag banks distinct
    __shared__ __align__(16) float Bs[2][16][136];   // 136 ≡ 8 mod 32: frag banks distinct

    const int tid  = threadIdx.x;
    const int lane = tid & 31;
    const int warp = tid >> 5;
    const int g    = lane >> 2;
    const int tig  = lane & 3;
    const int wm   = warp >> 1;      // 0..3
    const int wn   = warp & 1;       // 0..1
    const int m0   = blockIdx.y * 128;
    const int n0   = blockIdx.x * 128;

    // gmem tile-load coords
    const int arow0 = tid >> 2;              // 0..63 (+64 second half)
    const int ak    = (tid & 3) * 4;         // 0,4,8,12
    const int brow0 = tid >> 5;              // 0..7 (+8 second half)
    const int bcol  = (tid & 31) * 4;        // 0..124

    const float* Ap = A + (size_t)(m0 + arow0) * K + ak;
    const float* Bp = B + (size_t)brow0 * N + n0 + bcol;

    float4 areg0, areg1, breg0, breg1;

    float acc[2][8][4];
    #pragma unroll
    for (int mt = 0; mt < 2; mt++)
        #pragma unroll
        for (int nt = 0; nt < 8; nt++)
            #pragma unroll
            for (int i = 0; i < 4; i++) acc[mt][nt][i] = 0.0f;

    // prologue: load k-tile 0
    areg0 = *reinterpret_cast<const float4*>(Ap);
    areg1 = *reinterpret_cast<const float4*>(Ap + (size_t)64 * K);
    breg0 = *reinterpret_cast<const float4*>(Bp);
    breg1 = *reinterpret_cast<const float4*>(Bp + (size_t)8 * N);
    *reinterpret_cast<float4*>(&As[0][arow0][ak])      = cvt4(areg0);
    *reinterpret_cast<float4*>(&As[0][arow0 + 64][ak]) = cvt4(areg1);
    *reinterpret_cast<float4*>(&Bs[0][brow0][bcol])    = cvt4(breg0);
    *reinterpret_cast<float4*>(&Bs[0][brow0 + 8][bcol])= cvt4(breg1);
    __syncthreads();

    const int nsteps = K >> 4;
    for (int s = 0; s < nsteps; s++) {
        const int buf = s & 1;
        if (s + 1 < nsteps) {
            int k0 = (s + 1) << 4;
            areg0 = *reinterpret_cast<const float4*>(Ap + k0);
            areg1 = *reinterpret_cast<const float4*>(Ap + (size_t)64 * K + k0);
            breg0 = *reinterpret_cast<const float4*>(Bp + (size_t)k0 * N);
            breg1 = *reinterpret_cast<const float4*>(Bp + (size_t)(k0 + 8) * N);
        }

        #pragma unroll
        for (int half = 0; half < 2; half++) {
            const int kb = half * 8;
            float a[2][4], b[8][2];
            #pragma unroll
            for (int mt = 0; mt < 2; mt++) {
                const int r = wm * 32 + mt * 16;
                a[mt][0] = As[buf][r + g][kb + tig];
                a[mt][1] = As[buf][r + 8 + g][kb + tig];
                a[mt][2] = As[buf][r + g][kb + tig + 4];
                a[mt][3] = As[buf][r + 8 + g][kb + tig + 4];
            }
            #pragma unroll
            for (int nt = 0; nt < 8; nt++) {
                const int c = wn * 64 + nt * 8 + g;
                b[nt][0] = Bs[buf][kb + tig][c];
                b[nt][1] = Bs[buf][kb + tig + 4][c];
            }
            #pragma unroll
            for (int mt = 0; mt < 2; mt++)
                #pragma unroll
                for (int nt = 0; nt < 8; nt++)
                    mma8(acc[mt][nt], a[mt], b[nt]);
        }

        if (s + 1 < nsteps) {
            const int nb = buf ^ 1;
            *reinterpret_cast<float4*>(&As[nb][arow0][ak])      = cvt4(areg0);
            *reinterpret_cast<float4*>(&As[nb][arow0 + 64][ak]) = cvt4(areg1);
            *reinterpret_cast<float4*>(&Bs[nb][brow0][bcol])    = cvt4(breg0);
            *reinterpret_cast<float4*>(&Bs[nb][brow0 + 8][bcol])= cvt4(breg1);
        }
        __syncthreads();
    }

    // epilogue
    #pragma unroll
    for (int mt = 0; mt < 2; mt++) {
        const int r0 = m0 + wm * 32 + mt * 16 + g;
        const int r1 = r0 + 8;
        #pragma unroll
        for (int nt = 0; nt < 8; nt++) {
            const int c = n0 + wn * 64 + nt * 8 + tig * 2;
            const float b0 = bias[c], b1 = bias[c + 1];
            float v0 = acc[mt][nt][0] + b0;
            float v1 = acc[mt][nt][1] + b1;
            float v2 = acc[mt][nt][2] + b0;
            float v3 = acc[mt][nt][3] + b1;
            if (OP == 1) {
                const float2 ra = *reinterpret_cast<const float2*>(res + (size_t)r0 * N + c);
                const float2 rb = *reinterpret_cast<const float2*>(res + (size_t)r1 * N + c);
                v0 += ra.x; v1 += ra.y; v2 += rb.x; v3 += rb.y;
            }
            if (OP == 2) {
                v0 = 0.5f * v0 * (1.0f + erff(v0 * 0.70710678118654752f));
                v1 = 0.5f * v1 * (1.0f + erff(v1 * 0.70710678118654752f));
                v2 = 0.5f * v2 * (1.0f + erff(v2 * 0.70710678118654752f));
                v3 = 0.5f * v3 * (1.0f + erff(v3 * 0.70710678118654752f));
            }
            *reinterpret_cast<float2*>(C + (size_t)r0 * N + c) = make_float2(v0, v1);
            *reinterpret_cast<float2*>(C + (size_t)r1 * N + c) = make_float2(v2, v3);
        }
    }
}

// ---------------- split qkv, L2-normalize q,k; relayout to [H,L,64] --
__global__ __launch_bounds__(256) void qkvnorm_kernel(
    const float* __restrict__ qkv, float* __restrict__ Q,
    float* __restrict__ Km, float* __restrict__ V)
{
    int gw   = (blockIdx.x * blockDim.x + threadIdx.x) >> 5;
    int lane = threadIdx.x & 31;
    int l = gw >> 4;
    int h = gw & 15;

    const float* base = qkv + (size_t)l * (3 * DM);
    size_t oidx = ((size_t)h * SEQ + l) * HD + lane * 2;

    float2 qv = *reinterpret_cast<const float2*>(base + h * HD + lane * 2);
    float ssq = qv.x * qv.x + qv.y * qv.y;
    #pragma unroll
    for (int o = 16; o > 0; o >>= 1) ssq += __shfl_xor_sync(0xffffffffu, ssq, o);
    float scq = 0.125f / fmaxf(sqrtf(ssq), 1e-12f);
    *reinterpret_cast<float2*>(Q + oidx) = make_float2(qv.x * scq, qv.y * scq);

    float2 kv = *reinterpret_cast<const float2*>(base + DM + h * HD + lane * 2);
    float ssk = kv.x * kv.x + kv.y * kv.y;
    #pragma unroll
    for (int o = 16; o > 0; o >>= 1) ssk += __shfl_xor_sync(0xffffffffu, ssk, o);
    float sck = 1.0f / fmaxf(sqrtf(ssk), 1e-12f);
    *reinterpret_cast<float2*>(Km + oidx) = make_float2(kv.x * sck, kv.y * sck);

    float2 vv = *reinterpret_cast<const float2*>(base + 2 * DM + h * HD + lane * 2);
    *reinterpret_cast<float2*>(V + oidx) = vv;
}

// ---------------- attention (clip to [-10,10] => no online max) ------
__global__ __launch_bounds__(128) void attn_kernel(
    const float* __restrict__ Q, const float* __restrict__ Km,
    const float* __restrict__ V, const float* __restrict__ lcc,
    float* __restrict__ out)
{
    __shared__ __align__(16) float ks[64 * 64];
    __shared__ __align__(16) float vs[64 * 64];
    __shared__ float lccs[64];

    int h   = blockIdx.y;
    int tid = threadIdx.x;
    int l   = blockIdx.x * 128 + tid;

    const float* qp = Q + ((size_t)h * SEQ + l) * HD;
    float q[64];
    #pragma unroll
    for (int d = 0; d < 64; d++) q[d] = qp[d];

    float myl = lcc[l] * 0.05f;
    float acc[64] = {};
    float denom = 0.0f;

    for (int kb = 0; kb < SEQ; kb += 64) {
        __syncthreads();
        const float* kp = Km + ((size_t)h * SEQ + kb) * HD;
        const float* vp = V  + ((size_t)h * SEQ + kb) * HD;
        #pragma unroll
        for (int t = 0; t < 8; t++) {
            int f4 = t * 128 + tid;
            reinterpret_cast<float4*>(ks)[f4] = reinterpret_cast<const float4*>(kp)[f4];
            reinterpret_cast<float4*>(vs)[f4] = reinterpret_cast<const float4*>(vp)[f4];
        }
        if (tid < 64) lccs[tid] = lcc[kb + tid] * 0.05f;
        __syncthreads();

        #pragma unroll 1
        for (int j = 0; j < 64; j++) {
            const float* kr = ks + j * 64;
            float s0 = 0.f, s1 = 0.f, s2 = 0.f, s3 = 0.f;
            #pragma unroll
            for (int kk = 0; kk < 64; kk += 4) {
                s0 += q[kk + 0] * kr[kk + 0];
                s1 += q[kk + 1] * kr[kk + 1];
                s2 += q[kk + 2] * kr[kk + 2];
                s3 += q[kk + 3] * kr[kk + 3];
            }
            float s = (s0 + s1) + (s2 + s3) + myl + lccs[j];
            s = fminf(10.0f, fmaxf(-10.0f, s));
            float p = expf(s);
            denom += p;
            const float* vr = vs + j * 64;
            #pragma unroll
            for (int d = 0; d < 64; d++) acc[d] += p * vr[d];
        }
    }

    float inv = 1.0f / denom;
    float* op = out + (size_t)l * DM + h * 64;
    #pragma unroll
    for (int d = 0; d < 64; d++) op[d] = acc[d] * inv;
}

// ---------------- launch --------------------------------------------------------
extern "C" void kernel_launch(void* const* d_in, const int* in_sizes, int n_in,
                              void* d_out, int out_size)
{
    const float* x     = (const float*)d_in[0];
    const float* lcc   = (const float*)d_in[1];
    const float* w_qkv = (const float*)d_in[2];
    const float* b_qkv = (const float*)d_in[3];
    const float* w_out = (const float*)d_in[4];
    const float* b_out = (const float*)d_in[5];
    const float* ln1_g = (const float*)d_in[6];
    const float* ln1_b = (const float*)d_in[7];
    const float* ln2_g = (const float*)d_in[8];
    const float* ln2_b = (const float*)d_in[9];
    const float* w_ff1 = (const float*)d_in[10];
    const float* b_ff1 = (const float*)d_in[11];
    const float* w_ff2 = (const float*)d_in[12];
    const float* b_ff2 = (const float*)d_in[13];
    float* out = (float*)d_out;

    float *normed, *qkv, *q, *k, *v, *attn, *x2, *normed2, *ffh;
    cudaGetSymbolAddress((void**)&normed,  g_normed);
    cudaGetSymbolAddress((void**)&qkv,     g_qkv);
    cudaGetSymbolAddress((void**)&q,       g_q);
    cudaGetSymbolAddress((void**)&k,       g_k);
    cudaGetSymbolAddress((void**)&v,       g_v);
    cudaGetSymbolAddress((void**)&attn,    g_attn);
    cudaGetSymbolAddress((void**)&x2,      g_x2);
    cudaGetSymbolAddress((void**)&normed2, g_normed2);
    cudaGetSymbolAddress((void**)&ffh,     g_ffh);

    // 1. LN1
    ln_kernel<<<SEQ, 256>>>(x, ln1_g, ln1_b, normed);
    // 2. QKV projection: [2048,1024] @ [1024,3072]
    mma_gemm<0><<<dim3(3 * DM / 128, SEQ / 128), 256>>>(
        normed, w_qkv, b_qkv, nullptr, qkv, SEQ, 3 * DM, DM);
    // 3. split + cosine-normalize + relayout
    qkvnorm_kernel<<<(SEQ * NH * 32) / 256, 256>>>(qkv, q, k, v);
    // 4. attention
    attn_kernel<<<dim3(SEQ / 128, NH), 128>>>(q, k, v, lcc, attn);
    // 5. out projection + residual
    mma_gemm<1><<<dim3(DM / 128, SEQ / 128), 256>>>(
        attn, w_out, b_out, x, x2, SEQ, DM, DM);
    // 6. LN2
    ln_kernel<<<SEQ, 256>>>(x2, ln2_g, ln2_b, normed2);
    // 7. FF1 + exact GELU
    mma_gemm<2><<<dim3(DFF / 128, SEQ / 128), 256>>>(
        normed2, w_ff1, b_ff1, nullptr, ffh, SEQ, DFF, DM);
    // 8. FF2 + residual -> out
    mma_gemm<1><<<dim3(DM / 128, SEQ / 128), 256>>>(
        ffh, w_ff2, b_ff2, x2, out, SEQ, DM, DFF);
}

// round 3
// speedup vs baseline: 3.4557x; 1.6741x over previous
#include <cuda_runtime.h>
#include <math.h>

#define SEQ  2048
#define DM   1024
#define NH   16
#define HD   64
#define DFF  4096

// ---------------- scratch (no allocation allowed) ----------------
__device__ float g_normed [SEQ * DM];
__device__ float g_qkv    [SEQ * 3 * DM];
__device__ float g_q      [NH * SEQ * HD];
__device__ float g_k      [NH * SEQ * HD];
__device__ float g_v      [NH * SEQ * HD];
__device__ float g_attn   [SEQ * DM];
__device__ float g_x2     [SEQ * DM];
__device__ float g_normed2[SEQ * DM];
__device__ float g_ffh    [SEQ * DFF];

// ---------------- LayerNorm ----------------
__global__ __launch_bounds__(256) void ln_kernel(
    const float* __restrict__ x, const float* __restrict__ g,
    const float* __restrict__ b, float* __restrict__ out)
{
    int row = blockIdx.x;
    int tid = threadIdx.x;
    const float* xr = x + (size_t)row * DM;
    float4 xv = reinterpret_cast<const float4*>(xr)[tid];
    float s  = xv.x + xv.y + xv.z + xv.w;
    float sq = xv.x*xv.x + xv.y*xv.y + xv.z*xv.z + xv.w*xv.w;

    __shared__ float sh1[256], sh2[256];
    sh1[tid] = s; sh2[tid] = sq;
    __syncthreads();
    #pragma unroll
    for (int o = 128; o > 0; o >>= 1) {
        if (tid < o) { sh1[tid] += sh1[tid + o]; sh2[tid] += sh2[tid + o]; }
        __syncthreads();
    }
    float mu   = sh1[0] * (1.0f / DM);
    float var  = sh2[0] * (1.0f / DM) - mu * mu;
    float rstd = rsqrtf(var + 1e-5f);

    float4 gv = reinterpret_cast<const float4*>(g)[tid];
    float4 bv = reinterpret_cast<const float4*>(b)[tid];
    float4 o4;
    o4.x = (xv.x - mu) * rstd * gv.x + bv.x;
    o4.y = (xv.y - mu) * rstd * gv.y + bv.y;
    o4.z = (xv.z - mu) * rstd * gv.z + bv.z;
    o4.w = (xv.w - mu) * rstd * gv.w + bv.w;
    reinterpret_cast<float4*>(out + (size_t)row * DM)[tid] = o4;
}

// ---------------- tf32 helpers ----------------
__device__ __forceinline__ float tf32r(float x) {
    float y;
    asm("cvt.rna.tf32.f32 %0, %1;" : "=f"(y) : "f"(x));
    return y;
}
__device__ __forceinline__ float4 cvt4(float4 v) {
    v.x = tf32r(v.x); v.y = tf32r(v.y); v.z = tf32r(v.z); v.w = tf32r(v.w);
    return v;
}
__device__ __forceinline__ void mma8(float* d, const float* a, const float* b) {
    asm volatile(
        "mma.sync.aligned.m16n8k8.row.col.f32.tf32.tf32.f32 "
        "{%0,%1,%2,%3}, {%4,%5,%6,%7}, {%8,%9}, {%0,%1,%2,%3};\n"
        : "+f"(d[0]), "+f"(d[1]), "+f"(d[2]), "+f"(d[3])
        : "r"(__float_as_uint(a[0])), "r"(__float_as_uint(a[1])),
          "r"(__float_as_uint(a[2])), "r"(__float_as_uint(a[3])),
          "r"(__float_as_uint(b[0])), "r"(__float_as_uint(b[1])));
}

// ---------------- tf32 MMA GEMM: 128x128 tile, BK=16, double buffered --------
template<int OP>
__global__ __launch_bounds__(256) void mma_gemm(
    const float* __restrict__ A, const float* __restrict__ B,
    const float* __restrict__ bias, const float* __restrict__ res,
    float* __restrict__ C, int M, int N, int K)
{
    __shared__ __align__(16) float As[2][128][20];
    __shared__ __align__(16) float Bs[2][16][136];

    const int tid  = threadIdx.x;
    const int lane = tid & 31;
    const int warp = tid >> 5;
    const int g    = lane >> 2;
    const int tig  = lane & 3;
    const int wm   = warp >> 1;
    const int wn   = warp & 1;
    const int m0   = blockIdx.y * 128;
    const int n0   = blockIdx.x * 128;

    const int arow0 = tid >> 2;
    const int ak    = (tid & 3) * 4;
    const int brow0 = tid >> 5;
    const int bcol  = (tid & 31) * 4;

    const float* Ap = A + (size_t)(m0 + arow0) * K + ak;
    const float* Bp = B + (size_t)brow0 * N + n0 + bcol;

    float4 areg0, areg1, breg0, breg1;

    float acc[2][8][4];
    #pragma unroll
    for (int mt = 0; mt < 2; mt++)
        #pragma unroll
        for (int nt = 0; nt < 8; nt++)
            #pragma unroll
            for (int i = 0; i < 4; i++) acc[mt][nt][i] = 0.0f;

    areg0 = *reinterpret_cast<const float4*>(Ap);
    areg1 = *reinterpret_cast<const float4*>(Ap + (size_t)64 * K);
    breg0 = *reinterpret_cast<const float4*>(Bp);
    breg1 = *reinterpret_cast<const float4*>(Bp + (size_t)8 * N);
    *reinterpret_cast<float4*>(&As[0][arow0][ak])      = cvt4(areg0);
    *reinterpret_cast<float4*>(&As[0][arow0 + 64][ak]) = cvt4(areg1);
    *reinterpret_cast<float4*>(&Bs[0][brow0][bcol])    = cvt4(breg0);
    *reinterpret_cast<float4*>(&Bs[0][brow0 + 8][bcol])= cvt4(breg1);
    __syncthreads();

    const int nsteps = K >> 4;
    for (int s = 0; s < nsteps; s++) {
        const int buf = s & 1;
        if (s + 1 < nsteps) {
            int k0 = (s + 1) << 4;
            areg0 = *reinterpret_cast<const float4*>(Ap + k0);
            areg1 = *reinterpret_cast<const float4*>(Ap + (size_t)64 * K + k0);
            breg0 = *reinterpret_cast<const float4*>(Bp + (size_t)k0 * N);
            breg1 = *reinterpret_cast<const float4*>(Bp + (size_t)(k0 + 8) * N);
        }

        #pragma unroll
        for (int half = 0; half < 2; half++) {
            const int kb = half * 8;
            float a[2][4], b[8][2];
            #pragma unroll
            for (int mt = 0; mt < 2; mt++) {
                const int r = wm * 32 + mt * 16;
                a[mt][0] = As[buf][r + g][kb + tig];
                a[mt][1] = As[buf][r + 8 + g][kb + tig];
                a[mt][2] = As[buf][r + g][kb + tig + 4];
                a[mt][3] = As[buf][r + 8 + g][kb + tig + 4];
            }
            #pragma unroll
            for (int nt = 0; nt < 8; nt++) {
                const int c = wn * 64 + nt * 8 + g;
                b[nt][0] = Bs[buf][kb + tig][c];
                b[nt][1] = Bs[buf][kb + tig + 4][c];
            }
            #pragma unroll
            for (int mt = 0; mt < 2; mt++)
                #pragma unroll
                for (int nt = 0; nt < 8; nt++)
                    mma8(acc[mt][nt], a[mt], b[nt]);
        }

        if (s + 1 < nsteps) {
            const int nb = buf ^ 1;
            *reinterpret_cast<float4*>(&As[nb][arow0][ak])      = cvt4(areg0);
            *reinterpret_cast<float4*>(&As[nb][arow0 + 64][ak]) = cvt4(areg1);
            *reinterpret_cast<float4*>(&Bs[nb][brow0][bcol])    = cvt4(breg0);
            *reinterpret_cast<float4*>(&Bs[nb][brow0 + 8][bcol])= cvt4(breg1);
        }
        __syncthreads();
    }

    #pragma unroll
    for (int mt = 0; mt < 2; mt++) {
        const int r0 = m0 + wm * 32 + mt * 16 + g;
        const int r1 = r0 + 8;
        #pragma unroll
        for (int nt = 0; nt < 8; nt++) {
            const int c = n0 + wn * 64 + nt * 8 + tig * 2;
            const float b0 = bias[c], b1 = bias[c + 1];
            float v0 = acc[mt][nt][0] + b0;
            float v1 = acc[mt][nt][1] + b1;
            float v2 = acc[mt][nt][2] + b0;
            float v3 = acc[mt][nt][3] + b1;
            if (OP == 1) {
                const float2 ra = *reinterpret_cast<const float2*>(res + (size_t)r0 * N + c);
                const float2 rb = *reinterpret_cast<const float2*>(res + (size_t)r1 * N + c);
                v0 += ra.x; v1 += ra.y; v2 += rb.x; v3 += rb.y;
            }
            if (OP == 2) {
                v0 = 0.5f * v0 * (1.0f + erff(v0 * 0.70710678118654752f));
                v1 = 0.5f * v1 * (1.0f + erff(v1 * 0.70710678118654752f));
                v2 = 0.5f * v2 * (1.0f + erff(v2 * 0.70710678118654752f));
                v3 = 0.5f * v3 * (1.0f + erff(v3 * 0.70710678118654752f));
            }
            *reinterpret_cast<float2*>(C + (size_t)r0 * N + c) = make_float2(v0, v1);
            *reinterpret_cast<float2*>(C + (size_t)r1 * N + c) = make_float2(v2, v3);
        }
    }
}

// ---------------- split qkv, L2-normalize q,k; relayout to [H,L,64] --
__global__ __launch_bounds__(256) void qkvnorm_kernel(
    const float* __restrict__ qkv, float* __restrict__ Q,
    float* __restrict__ Km, float* __restrict__ V)
{
    int gw   = (blockIdx.x * blockDim.x + threadIdx.x) >> 5;
    int lane = threadIdx.x & 31;
    int l = gw >> 4;
    int h = gw & 15;

    const float* base = qkv + (size_t)l * (3 * DM);
    size_t oidx = ((size_t)h * SEQ + l) * HD + lane * 2;

    float2 qv = *reinterpret_cast<const float2*>(base + h * HD + lane * 2);
    float ssq = qv.x * qv.x + qv.y * qv.y;
    #pragma unroll
    for (int o = 16; o > 0; o >>= 1) ssq += __shfl_xor_sync(0xffffffffu, ssq, o);
    float scq = 0.125f / fmaxf(sqrtf(ssq), 1e-12f);
    *reinterpret_cast<float2*>(Q + oidx) = make_float2(qv.x * scq, qv.y * scq);

    float2 kv = *reinterpret_cast<const float2*>(base + DM + h * HD + lane * 2);
    float ssk = kv.x * kv.x + kv.y * kv.y;
    #pragma unroll
    for (int o = 16; o > 0; o >>= 1) ssk += __shfl_xor_sync(0xffffffffu, ssk, o);
    float sck = 1.0f / fmaxf(sqrtf(ssk), 1e-12f);
    *reinterpret_cast<float2*>(Km + oidx) = make_float2(kv.x * sck, kv.y * sck);

    float2 vv = *reinterpret_cast<const float2*>(base + 2 * DM + h * HD + lane * 2);
    *reinterpret_cast<float2*>(V + oidx) = vv;
}

// ---------------- MMA attention -----------------------------------------------
// grid (SEQ/128, NH), 256 thr = 8 warps x 16 query rows.
// Scores clipped to [-10,10] before softmax => plain sum-of-exp, no online max.
// Smem: Q tile (128x68) unioned with K/V tiles (2 x 64x68).
#define APAD 68
__global__ __launch_bounds__(256) void attn_mma_kernel(
    const float* __restrict__ Q, const float* __restrict__ Km,
    const float* __restrict__ V, const float* __restrict__ lcc,
    float* __restrict__ out)
{
    __shared__ __align__(16) float pool[128 * APAD];
    __shared__ float lccs[64];
    float* Qs = pool;                 // [128][APAD]
    float* Ks = pool;                 // [64][APAD]
    float* Vs = pool + 64 * APAD;     // [64][APAD]

    const int h    = blockIdx.y;
    const int m0   = blockIdx.x * 128;
    const int tid  = threadIdx.x;
    const int lane = tid & 31;
    const int warp = tid >> 5;
    const int g    = lane >> 2;
    const int tig  = lane & 3;

    // ---- stage Q tile into smem (tf32), then extract per-warp A-fragments ----
    {
        const float* Qg = Q + ((size_t)h * SEQ + m0) * HD;
        #pragma unroll
        for (int t = 0; t < 8; t++) {
            int idx = t * 256 + tid;          // 2048 float4 total
            int row = idx >> 4;
            int c4  = (idx & 15) * 4;
            float4 v = *reinterpret_cast<const float4*>(Qg + (size_t)row * HD + c4);
            *reinterpret_cast<float4*>(&Qs[row * APAD + c4]) = cvt4(v);
        }
    }
    __syncthreads();

    float qa[8][4];
    {
        const int r = warp * 16;
        #pragma unroll
        for (int kc = 0; kc < 8; kc++) {
            qa[kc][0] = Qs[(r + g)     * APAD + kc * 8 + tig];
            qa[kc][1] = Qs[(r + 8 + g) * APAD + kc * 8 + tig];
            qa[kc][2] = Qs[(r + g)     * APAD + kc * 8 + tig + 4];
            qa[kc][3] = Qs[(r + 8 + g) * APAD + kc * 8 + tig + 4];
        }
    }

    const float rb0 = lcc[m0 + warp * 16 + g]     * 0.05f;
    const float rb1 = lcc[m0 + warp * 16 + 8 + g] * 0.05f;

    float o[8][4];
    #pragma unroll
    for (int nt = 0; nt < 8; nt++)
        #pragma unroll
        for (int i = 0; i < 4; i++) o[nt][i] = 0.0f;
    float d0 = 0.0f, d1 = 0.0f;

    const int src0 = (g << 2) | (tig >> 1);
    const int src1 = src0 + 2;
    const bool odd = (tig & 1);

    for (int kt = 0; kt < SEQ; kt += 64) {
        __syncthreads();   // previous tile fully consumed (also Q-frag extraction done)
        // load K,V 64x64 tiles (tf32)
        {
            const float* Kg = Km + ((size_t)h * SEQ + kt) * HD;
            const float* Vg = V  + ((size_t)h * SEQ + kt) * HD;
            int row = tid >> 4;
            int c4  = (tid & 15) * 4;
            #pragma unroll
            for (int t = 0; t < 4; t++) {
                int r = row + t * 16;
                float4 kv = *reinterpret_cast<const float4*>(Kg + (size_t)r * HD + c4);
                float4 vv = *reinterpret_cast<const float4*>(Vg + (size_t)r * HD + c4);
                *reinterpret_cast<float4*>(&Ks[r * APAD + c4]) = cvt4(kv);
                *reinterpret_cast<float4*>(&Vs[r * APAD + c4]) = cvt4(vv);
            }
            if (tid < 64) lccs[tid] = lcc[kt + tid] * 0.05f;
        }
        __syncthreads();

        // ---- S = Q @ K^T : 16x64 per warp ----
        float s[8][4];
        #pragma unroll
        for (int nt = 0; nt < 8; nt++)
            #pragma unroll
            for (int i = 0; i < 4; i++) s[nt][i] = 0.0f;

        #pragma unroll
        for (int kc = 0; kc < 8; kc++) {
            #pragma unroll
            for (int nt = 0; nt < 8; nt++) {
                float b[2];
                b[0] = Ks[(nt * 8 + g) * APAD + kc * 8 + tig];
                b[1] = Ks[(nt * 8 + g) * APAD + kc * 8 + tig + 4];
                mma8(s[nt], qa[kc], b);
            }
        }

        // ---- softmax numerators: p = exp(clip(s + b_i + b_j)), tf32-rounded ----
        #pragma unroll
        for (int nt = 0; nt < 8; nt++) {
            float cb0 = lccs[nt * 8 + tig * 2];
            float cb1 = lccs[nt * 8 + tig * 2 + 1];
            float v0 = s[nt][0] + rb0 + cb0;
            float v1 = s[nt][1] + rb0 + cb1;
            float v2 = s[nt][2] + rb1 + cb0;
            float v3 = s[nt][3] + rb1 + cb1;
            v0 = fminf(10.0f, fmaxf(-10.0f, v0));
            v1 = fminf(10.0f, fmaxf(-10.0f, v1));
            v2 = fminf(10.0f, fmaxf(-10.0f, v2));
            v3 = fminf(10.0f, fmaxf(-10.0f, v3));
            float p0 = tf32r(__expf(v0));
            float p1 = tf32r(__expf(v1));
            float p2 = tf32r(__expf(v2));
            float p3 = tf32r(__expf(v3));
            s[nt][0] = p0; s[nt][1] = p1; s[nt][2] = p2; s[nt][3] = p3;
            d0 += p0 + p1;
            d1 += p2 + p3;
        }

        // ---- O += P @ V ----
        #pragma unroll
        for (int kc = 0; kc < 8; kc++) {
            // re-layout P c-fragment -> a-fragment via shuffles
            float t00 = __shfl_sync(0xffffffffu, s[kc][0], src0);
            float t01 = __shfl_sync(0xffffffffu, s[kc][1], src0);
            float t02 = __shfl_sync(0xffffffffu, s[kc][2], src0);
            float t03 = __shfl_sync(0xffffffffu, s[kc][3], src0);
            float t10 = __shfl_sync(0xffffffffu, s[kc][0], src1);
            float t11 = __shfl_sync(0xffffffffu, s[kc][1], src1);
            float t12 = __shfl_sync(0xffffffffu, s[kc][2], src1);
            float t13 = __shfl_sync(0xffffffffu, s[kc][3], src1);
            float a[4];
            a[0] = odd ? t01 : t00;
            a[1] = odd ? t03 : t02;
            a[2] = odd ? t11 : t10;
            a[3] = odd ? t13 : t12;
            #pragma unroll
            for (int nt = 0; nt < 8; nt++) {
                float b[2];
                b[0] = Vs[(kc * 8 + tig)     * APAD + nt * 8 + g];
                b[1] = Vs[(kc * 8 + tig + 4) * APAD + nt * 8 + g];
                mma8(o[nt], a, b);
            }
        }
    }

    // ---- finalize: reduce denominators within quads, scale, store ----
    d0 += __shfl_xor_sync(0xffffffffu, d0, 1);
    d0 += __shfl_xor_sync(0xffffffffu, d0, 2);
    d1 += __shfl_xor_sync(0xffffffffu, d1, 1);
    d1 += __shfl_xor_sync(0xffffffffu, d1, 2);
    const float inv0 = 1.0f / d0;
    const float inv1 = 1.0f / d1;

    const int r0 = m0 + warp * 16 + g;
    const int r1 = r0 + 8;
    #pragma unroll
    for (int nt = 0; nt < 8; nt++) {
        const int c = h * HD + nt * 8 + tig * 2;
        *reinterpret_cast<float2*>(out + (size_t)r0 * DM + c) =
            make_float2(o[nt][0] * inv0, o[nt][1] * inv0);
        *reinterpret_cast<float2*>(out + (size_t)r1 * DM + c) =
            make_float2(o[nt][2] * inv1, o[nt][3] * inv1);
    }
}

// ---------------- launch --------------------------------------------------------
extern "C" void kernel_launch(void* const* d_in, const int* in_sizes, int n_in,
                              void* d_out, int out_size)
{
    const float* x     = (const float*)d_in[0];
    const float* lcc   = (const float*)d_in[1];
    const float* w_qkv = (const float*)d_in[2];
    const float* b_qkv = (const float*)d_in[3];
    const float* w_out = (const float*)d_in[4];
    const float* b_out = (const float*)d_in[5];
    const float* ln1_g = (const float*)d_in[6];
    const float* ln1_b = (const float*)d_in[7];
    const float* ln2_g = (const float*)d_in[8];
    const float* ln2_b = (const float*)d_in[9];
    const float* w_ff1 = (const float*)d_in[10];
    const float* b_ff1 = (const float*)d_in[11];
    const float* w_ff2 = (const float*)d_in[12];
    const float* b_ff2 = (const float*)d_in[13];
    float* out = (float*)d_out;

    float *normed, *qkv, *q, *k, *v, *attn, *x2, *normed2, *ffh;
    cudaGetSymbolAddress((void**)&normed,  g_normed);
    cudaGetSymbolAddress((void**)&qkv,     g_qkv);
    cudaGetSymbolAddress((void**)&q,       g_q);
    cudaGetSymbolAddress((void**)&k,       g_k);
    cudaGetSymbolAddress((void**)&v,       g_v);
    cudaGetSymbolAddress((void**)&attn,    g_attn);
    cudaGetSymbolAddress((void**)&x2,      g_x2);
    cudaGetSymbolAddress((void**)&normed2, g_normed2);
    cudaGetSymbolAddress((void**)&ffh,     g_ffh);

    // 1. LN1
    ln_kernel<<<SEQ, 256>>>(x, ln1_g, ln1_b, normed);
    // 2. QKV projection
    mma_gemm<0><<<dim3(3 * DM / 128, SEQ / 128), 256>>>(
        normed, w_qkv, b_qkv, nullptr, qkv, SEQ, 3 * DM, DM);
    // 3. split + cosine-normalize + relayout
    qkvnorm_kernel<<<(SEQ * NH * 32) / 256, 256>>>(qkv, q, k, v);
    // 4. attention (tf32 MMA)
    attn_mma_kernel<<<dim3(SEQ / 128, NH), 256>>>(q, k, v, lcc, attn);
    // 5. out projection + residual
    mma_gemm<1><<<dim3(DM / 128, SEQ / 128), 256>>>(
        attn, w_out, b_out, x, x2, SEQ, DM, DM);
    // 6. LN2
    ln_kernel<<<SEQ, 256>>>(x2, ln2_g, ln2_b, normed2);
    // 7. FF1 + exact GELU
    mma_gemm<2><<<dim3(DFF / 128, SEQ / 128), 256>>>(
        normed2, w_ff1, b_ff1, nullptr, ffh, SEQ, DFF, DM);
    // 8. FF2 + residual -> out
    mma_gemm<1><<<dim3(DM / 128, SEQ / 128), 256>>>(
        ffh, w_ff2, b_ff2, x2, out, SEQ, DM, DFF);
}